// round 12
// baseline (speedup 1.0000x reference)
#include <cuda_runtime.h>
#include <cstdint>

#define BATCH 8
#define SEQ   1024
#define DIM   1024
#define HEADS 16
#define DH    64
#define INNER 1024
#define QKV_STRIDE (3 * INNER)

// Scratch (static device arrays: the sanctioned no-alloc workaround)
__device__ uint32_t g_qkv[(size_t)BATCH * SEQ * 3 * INNER];   // tf32 bits
__device__ uint32_t g_att[(size_t)BATCH * SEQ * INNER];       // tf32 bits
__device__ uint32_t g_xt[(size_t)BATCH * SEQ * DIM];          // x as tf32 bits
__device__ uint32_t g_wqkvt[(size_t)DIM * 3 * INNER];         // w_qkv as tf32 bits
__device__ uint32_t g_woutt[(size_t)INNER * DIM];             // w_out as tf32 bits

// ---------------------------------------------------------------------------
// helpers
// ---------------------------------------------------------------------------
__device__ __forceinline__ uint32_t f2t(float x) {
    uint32_t r;
    asm("cvt.rna.tf32.f32 %0, %1;" : "=r"(r) : "f"(x));
    return r;
}
__device__ __forceinline__ uint4 f2t4(float4 v) {
    return make_uint4(f2t(v.x), f2t(v.y), f2t(v.z), f2t(v.w));
}
__device__ __forceinline__ float ex2(float x) {
    float r;
    asm("ex2.approx.ftz.f32 %0, %1;" : "=f"(r) : "f"(x));
    return r;
}
__device__ __forceinline__ uint32_t smem_u32(const void* p) {
    uint32_t a;
    asm("{ .reg .u64 t; cvta.to.shared.u64 t, %1; cvt.u32.u64 %0, t; }" : "=r"(a) : "l"(p));
    return a;
}
__device__ __forceinline__ void cpasync16(uint32_t s, const void* g) {
    asm volatile("cp.async.cg.shared.global [%0], [%1], 16;" :: "r"(s), "l"(g));
}

// m16n8k8 tf32 MMA, fp32 accumulate. A row-major, B col-major.
__device__ __forceinline__ void mma8(float* c, const uint32_t* a, const uint32_t* b) {
    asm volatile(
        "mma.sync.aligned.m16n8k8.row.col.f32.tf32.tf32.f32 "
        "{%0,%1,%2,%3}, {%4,%5,%6,%7}, {%8,%9}, {%0,%1,%2,%3};\n"
        : "+f"(c[0]), "+f"(c[1]), "+f"(c[2]), "+f"(c[3])
        : "r"(a[0]), "r"(a[1]), "r"(a[2]), "r"(a[3]), "r"(b[0]), "r"(b[1]));
}

// ---------------------------------------------------------------------------
// fp32 -> tf32-bits converter
// ---------------------------------------------------------------------------
__global__ void conv_tf32(const float4* __restrict__ in, uint4* __restrict__ out, int n4) {
    for (int i = blockIdx.x * blockDim.x + threadIdx.x; i < n4; i += gridDim.x * blockDim.x)
        out[i] = f2t4(in[i]);
}

// ---------------------------------------------------------------------------
// tf32 GEMM on pre-converted bits: C = A*B (+bias).
// BM=BN=128, BK=32, 256 threads, 8 warps (2m x 4n), warp tile 64x32.
// 3-stage cp.async pipeline (issue-before-compute); As [m][k] LDA2=36,
// Bs [k][n] LDB=136 (both conflict-free for fragment access).
// ---------------------------------------------------------------------------
#define LDA2 36
#define LDB 136
#define STG_WORDS (128 * LDA2 + 32 * LDB)          // 8960 words / stage
#define GEMM_SMEM (3 * STG_WORDS * 4)              // 107520 bytes

__global__ __launch_bounds__(256, 2) void gemm_tf32(
    const uint32_t* __restrict__ A, const uint32_t* __restrict__ B,
    const float* __restrict__ bias, uint32_t* __restrict__ C,
    int M, int N, int K, int out_tf32)
{
    extern __shared__ uint32_t sm[];
    const uint32_t sbase = smem_u32(sm);

    const int tid  = threadIdx.x;
    const int lane = tid & 31;
    const int warp = tid >> 5;
    const int row0 = blockIdx.y * 128;
    const int col0 = blockIdx.x * 128;

    const int wm = (warp >> 2) * 64;
    const int wn = (warp & 3) * 32;
    const int r4 = lane >> 2, c4 = lane & 3;

    float acc[4][4][4] = {};

    const int nch = K / 32;

    auto issue = [&](int c, int st) {
        const int kt = c * 32;
        const uint32_t abase = sbase + st * STG_WORDS * 4;
        const uint32_t bbase = abase + 128 * LDA2 * 4;
        #pragma unroll
        for (int it = 0; it < 4; it++) {
            int idx = tid + it * 256;                 // 0..1023
            int m = idx >> 3, kq = idx & 7;
            cpasync16(abase + (m * LDA2 + kq * 4) * 4,
                      A + (size_t)(row0 + m) * K + kt + kq * 4);
            int kr = idx >> 5, nq = (idx & 31) * 4;
            cpasync16(bbase + (kr * LDB + nq) * 4,
                      B + (size_t)(kt + kr) * N + col0 + nq);
        }
        asm volatile("cp.async.commit_group;" ::: "memory");
    };

    issue(0, 0);
    issue(1, 1);

    for (int c = 0; c < nch; c++) {
        if (c < nch - 1) asm volatile("cp.async.wait_group 1;" ::: "memory");
        else             asm volatile("cp.async.wait_group 0;" ::: "memory");
        __syncthreads();

        if (c + 2 < nch) issue(c + 2, (c + 2) % 3);

        const uint32_t* As = sm + (c % 3) * STG_WORDS;
        const uint32_t* Bs = As + 128 * LDA2;

        #pragma unroll
        for (int kk = 0; kk < 4; kk++) {
            const int kc = kk * 8 + c4;
            uint32_t a[4][4], b[4][2];
            #pragma unroll
            for (int fm = 0; fm < 4; fm++) {
                const int r = wm + fm * 16 + r4;
                a[fm][0] = As[r * LDA2 + kc];
                a[fm][1] = As[(r + 8) * LDA2 + kc];
                a[fm][2] = As[r * LDA2 + kc + 4];
                a[fm][3] = As[(r + 8) * LDA2 + kc + 4];
            }
            #pragma unroll
            for (int fn = 0; fn < 4; fn++) {
                const int n = wn + fn * 8 + r4;
                b[fn][0] = Bs[kc * LDB + n];
                b[fn][1] = Bs[(kc + 4) * LDB + n];
            }
            #pragma unroll
            for (int fm = 0; fm < 4; fm++)
                #pragma unroll
                for (int fn = 0; fn < 4; fn++)
                    mma8(acc[fm][fn], a[fm], b[fn]);
        }
    }

    // Epilogue
    #pragma unroll
    for (int fm = 0; fm < 4; fm++) {
        #pragma unroll
        for (int fn = 0; fn < 4; fn++) {
            const int row = row0 + wm + fm * 16 + r4;
            const int col = col0 + wn + fn * 8 + c4 * 2;
            uint32_t* c0 = C + (size_t)row * N + col;
            uint32_t* c1 = C + (size_t)(row + 8) * N + col;
            if (out_tf32) {
                *(uint2*)c0 = make_uint2(f2t(acc[fm][fn][0]), f2t(acc[fm][fn][1]));
                *(uint2*)c1 = make_uint2(f2t(acc[fm][fn][2]), f2t(acc[fm][fn][3]));
            } else {
                float b0 = 0.f, b1 = 0.f;
                if (bias) { b0 = bias[col]; b1 = bias[col + 1]; }
                *(float2*)c0 = make_float2(acc[fm][fn][0] + b0, acc[fm][fn][1] + b1);
                *(float2*)c1 = make_float2(acc[fm][fn][2] + b0, acc[fm][fn][3] + b1);
            }
        }
    }
}

// ---------------------------------------------------------------------------
// Flash attention (unchanged from R11 — known good at ~234us).
// CTA = 128 query rows of one (b,h); 128 threads, 4 warps; warp owns 32 rows
// (2 m-tiles) x 64 cols. Q frags in regs; exp2-domain softmax; swizzled V^T.
// ---------------------------------------------------------------------------
#define KVPAD 68
#define ATTN_SMEM ((2 * 64 * KVPAD + 4 * 2048) * 4)   // 67584 bytes

__global__ __launch_bounds__(128) void attn_tf32(
    const uint32_t* __restrict__ qkv, uint32_t* __restrict__ out)
{
    extern __shared__ uint32_t sm[];
    uint32_t* Ksm = sm;                     // [j(64)][KVPAD]
    uint32_t* Vsm = sm + 64 * KVPAD;        // [d(64)][ j ^ 4*((d>>3)&7) ]
    uint32_t* Psm = sm + 2 * 64 * KVPAD;    // per-warp 2048 words

    const int tid  = threadIdx.x;
    const int lane = tid & 31;
    const int warp = tid >> 5;
    const int r4 = lane >> 2, c4 = lane & 3;
    const int qt = blockIdx.x, h = blockIdx.y, b = blockIdx.z;
    const int qr0 = qt * 128 + warp * 32;

    const uint32_t* qbase = qkv + ((size_t)b * SEQ + qr0) * QKV_STRIDE + h * DH;
    const uint32_t* kbase = qkv + (size_t)b * SEQ * QKV_STRIDE + INNER     + h * DH;
    const uint32_t* vbase = qkv + (size_t)b * SEQ * QKV_STRIDE + 2 * INNER + h * DH;

    const float QS = 0.125f * 1.44269504088896340736f;
    uint32_t qf[8][2][4];
    #pragma unroll
    for (int kb = 0; kb < 8; kb++) {
        const int col = kb * 8 + c4;
        #pragma unroll
        for (int m2 = 0; m2 < 2; m2++) {
            const int rb = m2 * 16;
            qf[kb][m2][0] = f2t(__uint_as_float(qbase[(size_t)(rb + r4) * QKV_STRIDE + col]) * QS);
            qf[kb][m2][1] = f2t(__uint_as_float(qbase[(size_t)(rb + r4 + 8) * QKV_STRIDE + col]) * QS);
            qf[kb][m2][2] = f2t(__uint_as_float(qbase[(size_t)(rb + r4) * QKV_STRIDE + col + 4]) * QS);
            qf[kb][m2][3] = f2t(__uint_as_float(qbase[(size_t)(rb + r4 + 8) * QKV_STRIDE + col + 4]) * QS);
        }
    }

    float mrun[2][2] = {{-3.0e38f, -3.0e38f}, {-3.0e38f, -3.0e38f}};
    float lrun[2][2] = {{0.f, 0.f}, {0.f, 0.f}};
    float o[2][8][4] = {};
    uint32_t* Pw = Psm + warp * 2048;

    for (int t = 0; t < 16; t++) {
        __syncthreads();
        const uint32_t* kt_ = kbase + (size_t)t * 64 * QKV_STRIDE;
        const uint32_t* vt_ = vbase + (size_t)t * 64 * QKV_STRIDE;
        #pragma unroll
        for (int it = 0; it < 8; it++) {
            int idx = it * 128 + tid;            // 0..1023 uint4s
            int j = idx >> 4, dq = idx & 15;
            uint4 kv = *(const uint4*)(kt_ + (size_t)j * QKV_STRIDE + dq * 4);
            *(uint4*)&Ksm[j * KVPAD + dq * 4] = kv;
            uint4 vv = *(const uint4*)(vt_ + (size_t)j * QKV_STRIDE + dq * 4);
            const int swc = j ^ (4 * ((dq >> 1) & 7));
            Vsm[(dq * 4 + 0) * KVPAD + swc] = vv.x;
            Vsm[(dq * 4 + 1) * KVPAD + swc] = vv.y;
            Vsm[(dq * 4 + 2) * KVPAD + swc] = vv.z;
            Vsm[(dq * 4 + 3) * KVPAD + swc] = vv.w;
        }
        __syncthreads();

        // ---- S = Q * K^T ----
        float s[2][8][4] = {};
        #pragma unroll
        for (int kb = 0; kb < 8; kb++) {
            #pragma unroll
            for (int fn = 0; fn < 8; fn++) {
                uint32_t bb[2];
                bb[0] = Ksm[(fn * 8 + r4) * KVPAD + kb * 8 + c4];
                bb[1] = Ksm[(fn * 8 + r4) * KVPAD + kb * 8 + c4 + 4];
                mma8(s[0][fn], qf[kb][0], bb);
                mma8(s[1][fn], qf[kb][1], bb);
            }
        }

        // ---- online softmax (exp2 domain) ----
        #pragma unroll
        for (int m2 = 0; m2 < 2; m2++) {
            float mt0 = -3.0e38f, mt1 = -3.0e38f;
            #pragma unroll
            for (int fn = 0; fn < 8; fn++) {
                mt0 = fmaxf(mt0, fmaxf(s[m2][fn][0], s[m2][fn][1]));
                mt1 = fmaxf(mt1, fmaxf(s[m2][fn][2], s[m2][fn][3]));
            }
            mt0 = fmaxf(mt0, __shfl_xor_sync(0xffffffffu, mt0, 1));
            mt0 = fmaxf(mt0, __shfl_xor_sync(0xffffffffu, mt0, 2));
            mt1 = fmaxf(mt1, __shfl_xor_sync(0xffffffffu, mt1, 1));
            mt1 = fmaxf(mt1, __shfl_xor_sync(0xffffffffu, mt1, 2));
            const float mn0 = fmaxf(mrun[m2][0], mt0);
            const float mn1 = fmaxf(mrun[m2][1], mt1);
            const float al0 = ex2(mrun[m2][0] - mn0);
            const float al1 = ex2(mrun[m2][1] - mn1);
            float ls0 = 0.f, ls1 = 0.f;
            #pragma unroll
            for (int fn = 0; fn < 8; fn++) {
                s[m2][fn][0] = ex2(s[m2][fn][0] - mn0); ls0 += s[m2][fn][0];
                s[m2][fn][1] = ex2(s[m2][fn][1] - mn0); ls0 += s[m2][fn][1];
                s[m2][fn][2] = ex2(s[m2][fn][2] - mn1); ls1 += s[m2][fn][2];
                s[m2][fn][3] = ex2(s[m2][fn][3] - mn1); ls1 += s[m2][fn][3];
            }
            ls0 += __shfl_xor_sync(0xffffffffu, ls0, 1);
            ls0 += __shfl_xor_sync(0xffffffffu, ls0, 2);
            ls1 += __shfl_xor_sync(0xffffffffu, ls1, 1);
            ls1 += __shfl_xor_sync(0xffffffffu, ls1, 2);
            lrun[m2][0] = lrun[m2][0] * al0 + ls0;
            lrun[m2][1] = lrun[m2][1] * al1 + ls1;
            mrun[m2][0] = mn0;  mrun[m2][1] = mn1;

            #pragma unroll
            for (int fn = 0; fn < 8; fn++) {
                o[m2][fn][0] *= al0; o[m2][fn][1] *= al0;
                o[m2][fn][2] *= al1; o[m2][fn][3] *= al1;
            }

            const int lp0 = r4 * 4 + 2 * (c4 & 1);
            const int rb  = 2 * (c4 >> 1);
            uint32_t* Pm = Pw + m2 * 1024;
            #pragma unroll
            for (int fn = 0; fn < 8; fn++) {
                Pm[(fn * 4 + rb) * 32 + lp0]         = f2t(s[m2][fn][0]);
                Pm[(fn * 4 + rb) * 32 + lp0 + 1]     = f2t(s[m2][fn][1]);
                Pm[(fn * 4 + rb + 1) * 32 + lp0]     = f2t(s[m2][fn][2]);
                Pm[(fn * 4 + rb + 1) * 32 + lp0 + 1] = f2t(s[m2][fn][3]);
            }
        }
        __syncwarp();

        // ---- O += P * V ----
        #pragma unroll
        for (int kb = 0; kb < 8; kb++) {
            uint32_t a0[4], a1[4];
            #pragma unroll
            for (int r = 0; r < 4; r++) {
                a0[r] = Pw[(kb * 4 + r) * 32 + lane];
                a1[r] = Pw[1024 + (kb * 4 + r) * 32 + lane];
            }
            #pragma unroll
            for (int fn = 0; fn < 8; fn++) {
                const int d = fn * 8 + r4;
                const int sw = 4 * fn;
                uint32_t bb[2];
                bb[0] = Vsm[d * KVPAD + ((kb * 8 + c4) ^ sw)];
                bb[1] = Vsm[d * KVPAD + ((kb * 8 + c4 + 4) ^ sw)];
                mma8(o[0][fn], a0, bb);
                mma8(o[1][fn], a1, bb);
            }
        }
        __syncwarp();
    }

    // ---- normalize, emit tf32 bits for GEMM2 ----
    #pragma unroll
    for (int m2 = 0; m2 < 2; m2++) {
        const float inv0 = 1.f / lrun[m2][0];
        const float inv1 = 1.f / lrun[m2][1];
        uint32_t* ob = out + ((size_t)b * SEQ + qr0 + m2 * 16) * INNER + h * DH;
        #pragma unroll
        for (int fn = 0; fn < 8; fn++) {
            const int col = fn * 8 + 2 * c4;
            *(uint2*)&ob[(size_t)r4 * INNER + col] =
                make_uint2(f2t(o[m2][fn][0] * inv0), f2t(o[m2][fn][1] * inv0));
            *(uint2*)&ob[(size_t)(r4 + 8) * INNER + col] =
                make_uint2(f2t(o[m2][fn][2] * inv1), f2t(o[m2][fn][3] * inv1));
        }
    }
}

// ---------------------------------------------------------------------------
// Launch
// ---------------------------------------------------------------------------
extern "C" void kernel_launch(void* const* d_in, const int* in_sizes, int n_in,
                              void* d_out, int out_size)
{
    const float* x      = (const float*)d_in[0];
    const float* w_qkv  = (const float*)d_in[1];
    const float* w_out  = (const float*)d_in[2];
    const float* b_out  = (const float*)d_in[3];
    uint32_t* out = (uint32_t*)d_out;

    uint32_t *qkv, *att, *xt, *wqkvt, *woutt;
    cudaGetSymbolAddress((void**)&qkv,   g_qkv);
    cudaGetSymbolAddress((void**)&att,   g_att);
    cudaGetSymbolAddress((void**)&xt,    g_xt);
    cudaGetSymbolAddress((void**)&wqkvt, g_wqkvt);
    cudaGetSymbolAddress((void**)&woutt, g_woutt);

    const int M = BATCH * SEQ;   // 8192

    cudaFuncSetAttribute(gemm_tf32, cudaFuncAttributeMaxDynamicSharedMemorySize, GEMM_SMEM);
    cudaFuncSetAttribute(attn_tf32, cudaFuncAttributeMaxDynamicSharedMemorySize, ATTN_SMEM);

    // 0) pre-convert operands to tf32 bits
    conv_tf32<<<2048, 256>>>((const float4*)x,     (uint4*)xt,    (int)((size_t)M * DIM / 4));
    conv_tf32<<<1024, 256>>>((const float4*)w_qkv, (uint4*)wqkvt, (int)((size_t)DIM * 3 * INNER / 4));
    conv_tf32<<<512,  256>>>((const float4*)w_out, (uint4*)woutt, (int)((size_t)INNER * DIM / 4));

    // 1) QKV projection (emits tf32 bits)
    gemm_tf32<<<dim3(3 * INNER / 128, M / 128), 256, GEMM_SMEM>>>(
        xt, wqkvt, nullptr, qkv, M, 3 * INNER, DIM, 1);

    // 2) Flash attention (emits tf32 bits)
    attn_tf32<<<dim3(SEQ / 128, HEADS, BATCH), 128, ATTN_SMEM>>>(qkv, att);

    // 3) Output projection (fp32 + bias, final)
    gemm_tf32<<<dim3(DIM / 128, M / 128), 256, GEMM_SMEM>>>(
        att, woutt, b_out, out, M, DIM, INNER, 0);
}